// round 15
// baseline (speedup 1.0000x reference)
#include <cuda_runtime.h>
#include <math.h>

// Problem constants (fixed shapes from setup_inputs)
#define BI      8
#define SI      4
#define NPARTS  17
#define TAGD    1
#define CCH     ((1 + TAGD) * NPARTS)   // 34
#define HH      128
#define WW      128
#define HW      (HH * WW)               // 16384
#define NPERS   30
#define LTAG    (NPARTS * HW)           // 278528
#define EPSV    1e-6f

#define NTHREADS 128
// pull/push blocks FIRST (overlap their latency-bound gathers with the stream)
#define PP_BLOCKS   (BI * SI)                          // 32
// Det: fat streaming blocks. Each det block = one (b, chunk) column of 512
// elements (128 float4), looping over all 17 parts x 4 s. Mask float4 cached
// in registers across the whole loop -> mask traffic 1x (total = 45MB floor).
#define CHUNKS_PER_B 32
#define DET_BLOCKS  (BI * CHUNKS_PER_B)                // 256
#define TOTAL_BLOCKS (DET_BLOCKS + PP_BLOCKS)          // 288  (<= 296 = 2 CTA/SM, balanced)

// Per-block partials + completion counter (no device-side allocation allowed)
__device__ double g_scratch[TOTAL_BLOCKS];
__device__ unsigned int g_done = 0;   // reset by the last block each call

__global__ void __launch_bounds__(NTHREADS)
loss_fused_kernel(const float* __restrict__ preds,
                  const float* __restrict__ masks,
                  const float* __restrict__ heatmaps,
                  const int*   __restrict__ kp32,
                  float* __restrict__ out)
{
    const int bid = blockIdx.x;
    const int tid = threadIdx.x;
    const unsigned FULL = 0xffffffffu;

    __shared__ bool s_last;

    if (bid >= PP_BLOCKS) {
        // ---------------- det MSE partial (continuous stream) ----------------
        const int det_bid = bid - PP_BLOCKS;
        const int b     = det_bid >> 5;                 // / CHUNKS_PER_B
        const int chunk = det_bid & (CHUNKS_PER_B - 1);
        const int hw = (chunk * NTHREADS + tid) * 4;    // float4-aligned elem offset

        // Mask: loaded ONCE, reused for all 17 parts x 4 s.
        const float4 m4 = *reinterpret_cast<const float4*>(masks + (size_t)b * HW + hw);

        const float* hb_base = heatmaps + (size_t)b * NPARTS * HW + hw;
        const float* pb_base = preds    + (size_t)b * SI * CCH * HW + hw;

        float acc = 0.0f;
#pragma unroll 2
        for (int p = 0; p < NPARTS; p++) {
            // 5 independent LDG.128 per iteration; unroll 2 -> ~10 in flight.
            const float4 h4  = *reinterpret_cast<const float4*>(hb_base + (size_t)p * HW);
            const float4 p40 = *reinterpret_cast<const float4*>(pb_base + ((size_t)(0 * CCH) + p) * HW);
            const float4 p41 = *reinterpret_cast<const float4*>(pb_base + ((size_t)(1 * CCH) + p) * HW);
            const float4 p42 = *reinterpret_cast<const float4*>(pb_base + ((size_t)(2 * CCH) + p) * HW);
            const float4 p43 = *reinterpret_cast<const float4*>(pb_base + ((size_t)(3 * CCH) + p) * HW);

            {
                const float dx = p40.x - h4.x, dy = p40.y - h4.y;
                const float dz = p40.z - h4.z, dw = p40.w - h4.w;
                acc += dx * dx * m4.x + dy * dy * m4.y + dz * dz * m4.z + dw * dw * m4.w;
            }
            {
                const float dx = p41.x - h4.x, dy = p41.y - h4.y;
                const float dz = p41.z - h4.z, dw = p41.w - h4.w;
                acc += dx * dx * m4.x + dy * dy * m4.y + dz * dz * m4.z + dw * dw * m4.w;
            }
            {
                const float dx = p42.x - h4.x, dy = p42.y - h4.y;
                const float dz = p42.z - h4.z, dw = p42.w - h4.w;
                acc += dx * dx * m4.x + dy * dy * m4.y + dz * dz * m4.z + dw * dw * m4.w;
            }
            {
                const float dx = p43.x - h4.x, dy = p43.y - h4.y;
                const float dz = p43.z - h4.z, dw = p43.w - h4.w;
                acc += dx * dx * m4.x + dy * dy * m4.y + dz * dz * m4.z + dw * dw * m4.w;
            }
        }

        // block reduction (4 warps)
#pragma unroll
        for (int o = 16; o > 0; o >>= 1) acc += __shfl_xor_sync(FULL, acc, o);
        __shared__ float wsum[4];
        const int wid = tid >> 5;
        if ((tid & 31) == 0) wsum[wid] = acc;
        __syncthreads();
        if (tid == 0) {
            float s = wsum[0] + wsum[1] + wsum[2] + wsum[3];
            // pre-weighted: weight 1.0 * mean over (B,S,17,H,W)
            g_scratch[bid] = (double)s * (1.0 / ((double)BI * SI * NPARTS * HW));
        }
    } else {
        // ---------------- pull/push for one (b,s) ----------------
        const int b = bid / SI;
        const int s = bid % SI;

        __shared__ float gm[NPERS * NPARTS];   // g * vis
        __shared__ float vf[NPERS * NPARTS];   // vis as float
        __shared__ int   is64_s;

        // Detect keypoint dtype with one parallel warp pass:
        // int64 little-endian with values < 2^31 => all odd 32-bit words zero.
        if (tid < 32) {
            const int v = kp32[2 * tid + 1];   // odd words 1,3,...,63
            const unsigned nz = __ballot_sync(FULL, v != 0);
            if (tid == 0) is64_s = (nz == 0u) ? 1 : 0;
        }
        __syncthreads();
        const int is64 = is64_s;

        const float* tagbase = preds + ((size_t)(b * SI + s) * CCH + NPARTS) * HW;

        for (int i = tid; i < NPERS * NPARTS; i += NTHREADS) {
            const int p = i / NPARTS;
            const int k = i % NPARTS;
            const int e = (b * NPERS + p) * NPARTS + k;   // entry index
            int idx, visv;
            if (is64) { idx = kp32[4 * e];     visv = kp32[4 * e + 2]; }
            else      { idx = kp32[2 * e];     visv = kp32[2 * e + 1]; }
            const float v = (visv > 0) ? 1.0f : 0.0f;
            gm[i] = v * tagbase[idx];   // idx always in [0, LTAG)
            vf[i] = v;
        }
        __syncthreads();

        if (tid < 32) {
            const int p = tid;
            float cnt = 0.0f, sum = 0.0f;
            if (p < NPERS) {
#pragma unroll
                for (int k = 0; k < NPARTS; k++) {
                    cnt += vf[p * NPARTS + k];
                    sum += gm[p * NPARTS + k];
                }
            }
            const float validf = (p < NPERS && cnt > 0.0f) ? 1.0f : 0.0f;
            const float safe   = fmaxf(cnt, 1.0f);
            const float mean   = sum / safe;

            float pull_pp = 0.0f;
            if (p < NPERS) {
#pragma unroll
                for (int k = 0; k < NPARTS; k++) {
                    const float d = gm[p * NPARTS + k] - mean * vf[p * NPARTS + k];
                    pull_pp += d * d;
                }
            }
            pull_pp /= safe;   // TAG_DIM == 1

            const unsigned bal = __ballot_sync(FULL, validf > 0.0f);
            const float num = (float)__popc(bal);

            float pullv = pull_pp * validf;
#pragma unroll
            for (int o = 16; o > 0; o >>= 1) pullv += __shfl_xor_sync(FULL, pullv, o);
            const float pull_bs = pullv / (num + EPSV);

            float row = 0.0f;
            for (int q = 0; q < NPERS; q++) {
                const float mq = __shfl_sync(FULL, mean,   q);
                const float vq = __shfl_sync(FULL, validf, q);
                const float d  = mean - mq;
                row += vq * expf(-d * d);
            }
            row *= validf;
#pragma unroll
            for (int o = 16; o > 0; o >>= 1) row += __shfl_xor_sync(FULL, row, o);
            const float push_sum = row - num;
            const float push_bs  = push_sum / ((num - 1.0f) * num + EPSV) * 0.5f;

            if (tid == 0) {
                g_scratch[bid] = (double)(0.001f * (push_bs + pull_bs)) / (double)(BI * SI);
            }
        }
        __syncthreads();
    }

    // ---------- completion protocol: RELEASE-only atomic (no L1 invalidate) ----------
    // tid0's scratch store (same thread) is ordered before the counter update by
    // release semantics; the last block reads partials with __ldcg (L2-direct),
    // so no acquire / CCTL.IVALL is needed anywhere on the hot path.
    if (tid == 0) {
        unsigned prev;
        asm volatile("atom.release.gpu.global.add.u32 %0, [%1], 1;"
                     : "=r"(prev) : "l"(&g_done) : "memory");
        s_last = (prev == (unsigned)(TOTAL_BLOCKS - 1));
    }
    __syncthreads();

    if (s_last) {
        double acc = 0.0;
        // Fixed-order reduction -> deterministic regardless of which block runs it.
        for (int i = tid; i < TOTAL_BLOCKS; i += NTHREADS) {
            acc += __ldcg(&g_scratch[i]);
        }
#pragma unroll
        for (int o = 16; o > 0; o >>= 1) acc += __shfl_xor_sync(FULL, acc, o);
        __shared__ double wsum2[4];
        const int wid = tid >> 5;
        if ((tid & 31) == 0) wsum2[wid] = acc;
        __syncthreads();
        if (tid == 0) {
            double s = wsum2[0] + wsum2[1] + wsum2[2] + wsum2[3];
            out[0] = (float)s;
            g_done = 0;   // all blocks arrived; plain store, visible next launch
        }
    }
}

extern "C" void kernel_launch(void* const* d_in, const int* in_sizes, int n_in,
                              void* d_out, int out_size)
{
    (void)out_size;
    const float* preds    = nullptr;
    const float* masks    = nullptr;
    const float* heatmaps = nullptr;
    const int*   kp       = nullptr;

    // Identify inputs by element count (defensive vs. ordering)
    for (int i = 0; i < n_in; i++) {
        switch (in_sizes[i]) {
            case BI * SI * CCH * HW:   preds    = (const float*)d_in[i]; break;  // 17825792
            case BI * HW:              masks    = (const float*)d_in[i]; break;  // 131072
            case BI * NPARTS * HW:     heatmaps = (const float*)d_in[i]; break;  // 2228224
            case BI * NPERS * NPARTS * 2: kp    = (const int*)d_in[i];   break;  // 8160
            default: break;
        }
    }
    if (!preds    && n_in > 0) preds    = (const float*)d_in[0];
    if (!masks    && n_in > 1) masks    = (const float*)d_in[1];
    if (!heatmaps && n_in > 2) heatmaps = (const float*)d_in[2];
    if (!kp       && n_in > 3) kp       = (const int*)d_in[3];

    loss_fused_kernel<<<TOTAL_BLOCKS, NTHREADS>>>(preds, masks, heatmaps, kp, (float*)d_out);
}

// round 16
// speedup vs baseline: 1.3713x; 1.3713x over previous
#include <cuda_runtime.h>
#include <math.h>

// Problem constants (fixed shapes from setup_inputs)
#define BI      8
#define SI      4
#define NPARTS  17
#define TAGD    1
#define CCH     ((1 + TAGD) * NPARTS)   // 34
#define HH      128
#define WW      128
#define HW      (HH * WW)               // 16384
#define NPERS   30
#define LTAG    (NPARTS * HW)           // 278528
#define EPSV    1e-6f

#define NTHREADS 512
// pull/push blocks FIRST (overlap their latency-bound gathers with the stream)
#define PP_BLOCKS   (BI * SI)                          // 32
// Det: 1088 work items (136 planes x 8 chunks of 2048 elems); 544 persistent
// det blocks, each looping over 2 items -> pipelined back-to-back bursts.
#define CHUNKS_PER_PLANE 8
#define DET_ITEMS   (BI * NPARTS * CHUNKS_PER_PLANE)   // 1088
#define DET_BLOCKS  (DET_ITEMS / 2)                    // 544
#define TOTAL_BLOCKS (DET_BLOCKS + PP_BLOCKS)          // 576  (single wave @ 4 CTA/SM)

// Per-block partials + completion counter (no device-side allocation allowed)
__device__ double g_scratch[TOTAL_BLOCKS];
__device__ unsigned int g_done = 0;   // reset by the last block each call

__global__ void __launch_bounds__(NTHREADS, 4)
loss_fused_kernel(const float* __restrict__ preds,
                  const float* __restrict__ masks,
                  const float* __restrict__ heatmaps,
                  const int*   __restrict__ kp32,
                  float* __restrict__ out)
{
    const int bid = blockIdx.x;
    const int tid = threadIdx.x;
    const unsigned FULL = 0xffffffffu;

    __shared__ bool s_last;

    if (bid >= PP_BLOCKS) {
        // ---------------- det MSE partial (2 pipelined items) ----------------
        const int det_bid = bid - PP_BLOCKS;

        float acc = 0.0f;
#pragma unroll
        for (int k = 0; k < 2; k++) {
            const int item  = det_bid + k * DET_BLOCKS;   // [0, 1088)
            const int plane = item >> 3;                  // / CHUNKS_PER_PLANE
            const int chunk = item & (CHUNKS_PER_PLANE - 1);
            const int b = plane / NPARTS;
            const int p = plane % NPARTS;
            const int hw = chunk * 2048 + tid * 4;        // 512 thr * 4 elems

            const float4 m4 = *reinterpret_cast<const float4*>(
                masks + (size_t)b * HW + hw);
            const float4 h4 = *reinterpret_cast<const float4*>(
                heatmaps + ((size_t)b * NPARTS + p) * HW + hw);

#pragma unroll
            for (int s = 0; s < SI; s++) {
                const float4 p4 = *reinterpret_cast<const float4*>(
                    preds + (((size_t)(b * SI + s) * CCH + p) * HW + hw));
                const float dx = p4.x - h4.x;
                const float dy = p4.y - h4.y;
                const float dz = p4.z - h4.z;
                const float dw = p4.w - h4.w;
                acc += dx * dx * m4.x + dy * dy * m4.y + dz * dz * m4.z + dw * dw * m4.w;
            }
        }

        // block reduction (16 warps)
#pragma unroll
        for (int o = 16; o > 0; o >>= 1) acc += __shfl_xor_sync(FULL, acc, o);
        __shared__ float wsum[16];
        const int wid = tid >> 5;
        if ((tid & 31) == 0) wsum[wid] = acc;
        __syncthreads();
        if (tid == 0) {
            float s = 0.0f;
#pragma unroll
            for (int w = 0; w < 16; w++) s += wsum[w];
            // pre-weighted: weight 1.0 * mean over (B,S,17,H,W)
            g_scratch[bid] = (double)s * (1.0 / ((double)BI * SI * NPARTS * HW));
        }
    } else {
        // ---------------- pull/push for one (b,s) ----------------
        const int b = bid / SI;
        const int s = bid % SI;

        __shared__ float gm[NPERS * NPARTS];   // g * vis
        __shared__ float vf[NPERS * NPARTS];   // vis as float
        __shared__ int   is64_s;

        // Detect keypoint dtype with one parallel warp pass:
        // int64 little-endian with values < 2^31 => all odd 32-bit words zero.
        if (tid < 32) {
            const int v = kp32[2 * tid + 1];   // odd words 1,3,...,63
            const unsigned nz = __ballot_sync(FULL, v != 0);
            if (tid == 0) is64_s = (nz == 0u) ? 1 : 0;
        }
        __syncthreads();
        const int is64 = is64_s;

        const float* tagbase = preds + ((size_t)(b * SI + s) * CCH + NPARTS) * HW;

        for (int i = tid; i < NPERS * NPARTS; i += NTHREADS) {
            const int p = i / NPARTS;
            const int k = i % NPARTS;
            const int e = (b * NPERS + p) * NPARTS + k;   // entry index
            int idx, visv;
            if (is64) { idx = kp32[4 * e];     visv = kp32[4 * e + 2]; }
            else      { idx = kp32[2 * e];     visv = kp32[2 * e + 1]; }
            const float v = (visv > 0) ? 1.0f : 0.0f;
            gm[i] = v * tagbase[idx];   // idx always in [0, LTAG)
            vf[i] = v;
        }
        __syncthreads();

        if (tid < 32) {
            const int p = tid;
            float cnt = 0.0f, sum = 0.0f;
            if (p < NPERS) {
#pragma unroll
                for (int k = 0; k < NPARTS; k++) {
                    cnt += vf[p * NPARTS + k];
                    sum += gm[p * NPARTS + k];
                }
            }
            const float validf = (p < NPERS && cnt > 0.0f) ? 1.0f : 0.0f;
            const float safe   = fmaxf(cnt, 1.0f);
            const float mean   = sum / safe;

            float pull_pp = 0.0f;
            if (p < NPERS) {
#pragma unroll
                for (int k = 0; k < NPARTS; k++) {
                    const float d = gm[p * NPARTS + k] - mean * vf[p * NPARTS + k];
                    pull_pp += d * d;
                }
            }
            pull_pp /= safe;   // TAG_DIM == 1

            const unsigned bal = __ballot_sync(FULL, validf > 0.0f);
            const float num = (float)__popc(bal);

            float pullv = pull_pp * validf;
#pragma unroll
            for (int o = 16; o > 0; o >>= 1) pullv += __shfl_xor_sync(FULL, pullv, o);
            const float pull_bs = pullv / (num + EPSV);

            float row = 0.0f;
            for (int q = 0; q < NPERS; q++) {
                const float mq = __shfl_sync(FULL, mean,   q);
                const float vq = __shfl_sync(FULL, validf, q);
                const float d  = mean - mq;
                row += vq * expf(-d * d);
            }
            row *= validf;
#pragma unroll
            for (int o = 16; o > 0; o >>= 1) row += __shfl_xor_sync(FULL, row, o);
            const float push_sum = row - num;
            const float push_bs  = push_sum / ((num - 1.0f) * num + EPSV) * 0.5f;

            if (tid == 0) {
                g_scratch[bid] = (double)(0.001f * (push_bs + pull_bs)) / (double)(BI * SI);
            }
        }
        __syncthreads();
    }

    // ---------- completion protocol: RELEASE-only atomic (no L1 invalidate) ----------
    // tid0's scratch store (same thread) is ordered before the counter update by
    // release semantics; the last block reads partials with __ldcg (L2-direct),
    // so no acquire / CCTL.IVALL is needed anywhere on the hot path.
    if (tid == 0) {
        unsigned prev;
        asm volatile("atom.release.gpu.global.add.u32 %0, [%1], 1;"
                     : "=r"(prev) : "l"(&g_done) : "memory");
        s_last = (prev == (unsigned)(TOTAL_BLOCKS - 1));
    }
    __syncthreads();

    if (s_last) {
        double acc = 0.0;
        // Fixed-order reduction -> deterministic regardless of which block runs it.
        for (int i = tid; i < TOTAL_BLOCKS; i += NTHREADS) {
            acc += __ldcg(&g_scratch[i]);
        }
#pragma unroll
        for (int o = 16; o > 0; o >>= 1) acc += __shfl_xor_sync(FULL, acc, o);
        __shared__ double wsum2[16];
        const int wid = tid >> 5;
        if ((tid & 31) == 0) wsum2[wid] = acc;
        __syncthreads();
        if (tid == 0) {
            double s = 0.0;
#pragma unroll
            for (int w = 0; w < 16; w++) s += wsum2[w];
            out[0] = (float)s;
            g_done = 0;   // all blocks arrived; plain store, visible next launch
        }
    }
}

extern "C" void kernel_launch(void* const* d_in, const int* in_sizes, int n_in,
                              void* d_out, int out_size)
{
    (void)out_size;
    const float* preds    = nullptr;
    const float* masks    = nullptr;
    const float* heatmaps = nullptr;
    const int*   kp       = nullptr;

    // Identify inputs by element count (defensive vs. ordering)
    for (int i = 0; i < n_in; i++) {
        switch (in_sizes[i]) {
            case BI * SI * CCH * HW:   preds    = (const float*)d_in[i]; break;  // 17825792
            case BI * HW:              masks    = (const float*)d_in[i]; break;  // 131072
            case BI * NPARTS * HW:     heatmaps = (const float*)d_in[i]; break;  // 2228224
            case BI * NPERS * NPARTS * 2: kp    = (const int*)d_in[i];   break;  // 8160
            default: break;
        }
    }
    if (!preds    && n_in > 0) preds    = (const float*)d_in[0];
    if (!masks    && n_in > 1) masks    = (const float*)d_in[1];
    if (!heatmaps && n_in > 2) heatmaps = (const float*)d_in[2];
    if (!kp       && n_in > 3) kp       = (const int*)d_in[3];

    loss_fused_kernel<<<TOTAL_BLOCKS, NTHREADS>>>(preds, masks, heatmaps, kp, (float*)d_out);
}